// round 15
// baseline (speedup 1.0000x reference)
#include <cuda_runtime.h>
#include <cuda_fp16.h>
#include <math.h>

#define NN 100000
#define EE 1600000
#define NB 98          // ceil(100000/1024)
#define G1_ROWS 64
#define G1_GRID ((NN + G1_ROWS - 1) / G1_ROWS)   // 1563
#define XS_STRIDE 132
#define G1_SMEM ((128 * XS_STRIDE + G1_ROWS * XS_STRIDE) * 4)

// ---------------- scratch (device globals; no allocation allowed) ----------
__device__ __half g_h1h[(size_t)NN * 128];  // layer-1 features (fp16)
__device__ __half g_out1h[(size_t)NN * 128];// layer-1 output (fp16, gemm2 input)
__device__ float g_as1[NN * 8];
__device__ float g_ad1[NN * 8];
__device__ __half g_h2h[(size_t)NN * 40];   // layer-2 features (fp16)
__device__ float g_a2s[NN];
__device__ float g_a2d[NN];
// CSR scratch
__device__ int g_cnt[NN];
__device__ int g_rowstart[NN + 1];
__device__ int g_cursor[NN];
__device__ int g_csrc[EE];
__device__ int g_bsum[NB];
__device__ int g_boff[NB];

// ---------------- side stream + events (static init: before harness baseline)
struct SideStream {
    cudaStream_t s;
    cudaEvent_t ea, eb;
    SideStream() {
        cudaStreamCreateWithFlags(&s, cudaStreamNonBlocking);
        cudaEventCreateWithFlags(&ea, cudaEventDisableTiming);
        cudaEventCreateWithFlags(&eb, cudaEventDisableTiming);
    }
};
static SideStream g_ss;

// ---------------- helpers ---------------------------------------------------
__device__ __forceinline__ unsigned long long pk2(float a, float b) {
    unsigned long long r;
    asm("mov.b64 %0, {%1,%2};" : "=l"(r) : "f"(a), "f"(b));
    return r;
}
__device__ __forceinline__ void upk2(unsigned long long v, float& a, float& b) {
    asm("mov.b64 {%0,%1}, %2;" : "=f"(a), "=f"(b) : "l"(v));
}
__device__ __forceinline__ void fma2(unsigned long long& d, unsigned long long a,
                                     unsigned long long b) {
    asm("fma.rn.f32x2 %0, %1, %2, %3;" : "=l"(d) : "l"(a), "l"(b), "l"(d));
}
__device__ __forceinline__ unsigned int tf32c(float f) {
    unsigned int u;
    asm("cvt.rna.tf32.f32 %0, %1;" : "=r"(u) : "f"(f));
    return u;
}
__device__ __forceinline__ float eluf(float x) { return x > 0.f ? x : expm1f(x); }
__device__ __forceinline__ float lrelu(float x) { return x > 0.f ? x : 0.2f * x; }

// ---------------- GEMM1 (tf32) + fused att1 logits ---------------------------
// h1h = fp16(X @ W1); as1/ad1 computed from fp32 accumulators in-register.
__global__ void gemm1_k(const float* __restrict__ X, const float* __restrict__ W,
                        const float* __restrict__ As1, const float* __restrict__ Ad1) {
    extern __shared__ unsigned int sm[];
    unsigned int* Ws = sm;                        // 128 x 132
    unsigned int* Xs = sm + 128 * XS_STRIDE;      // 64 x 132
    int tid = threadIdx.x;
    int row0 = blockIdx.x * G1_ROWS;

    for (int i = tid; i < 128 * 32; i += 128) {
        int k = i >> 5, n4 = (i & 31) * 4;
        float4 v = *(const float4*)(W + k * 128 + n4);
        unsigned int* p = Ws + k * XS_STRIDE + n4;
        p[0] = tf32c(v.x); p[1] = tf32c(v.y); p[2] = tf32c(v.z); p[3] = tf32c(v.w);
    }
    for (int i = tid; i < G1_ROWS * 32; i += 128) {
        int r = i >> 5, c4 = (i & 31) * 4;
        float4 v = make_float4(0.f, 0.f, 0.f, 0.f);
        if (row0 + r < NN) v = *(const float4*)(X + (size_t)(row0 + r) * 128 + c4);
        unsigned int* p = Xs + r * XS_STRIDE + c4;
        p[0] = tf32c(v.x); p[1] = tf32c(v.y); p[2] = tf32c(v.z); p[3] = tf32c(v.w);
    }
    __syncthreads();

    int w = tid >> 5;
    int lane = tid & 31;
    int g = lane >> 2;
    int t4 = lane & 3;

    float c[16][4];
    #pragma unroll
    for (int nt = 0; nt < 16; nt++)
        c[nt][0] = c[nt][1] = c[nt][2] = c[nt][3] = 0.f;

    int ar = w * 16 + g;
    #pragma unroll
    for (int k = 0; k < 16; k++) {
        unsigned int a0 = Xs[ar * XS_STRIDE + k * 8 + t4];
        unsigned int a1 = Xs[(ar + 8) * XS_STRIDE + k * 8 + t4];
        unsigned int a2 = Xs[ar * XS_STRIDE + k * 8 + t4 + 4];
        unsigned int a3 = Xs[(ar + 8) * XS_STRIDE + k * 8 + t4 + 4];
        #pragma unroll
        for (int nt = 0; nt < 16; nt++) {
            unsigned int b0 = Ws[(k * 8 + t4) * XS_STRIDE + nt * 8 + g];
            unsigned int b1 = Ws[(k * 8 + t4 + 4) * XS_STRIDE + nt * 8 + g];
            asm("mma.sync.aligned.m16n8k8.row.col.f32.tf32.tf32.f32 "
                "{%0,%1,%2,%3}, {%4,%5,%6,%7}, {%8,%9}, {%0,%1,%2,%3};"
                : "+f"(c[nt][0]), "+f"(c[nt][1]), "+f"(c[nt][2]), "+f"(c[nt][3])
                : "r"(a0), "r"(a1), "r"(a2), "r"(a3), "r"(b0), "r"(b1));
        }
    }

    int r0 = row0 + ar;
    int r1 = r0 + 8;
    // store fp16 h1h
    #pragma unroll
    for (int nt = 0; nt < 16; nt++) {
        int col = nt * 8 + t4 * 2;
        if (r0 < NN)
            *(__half2*)(g_h1h + (size_t)r0 * 128 + col) =
                __floats2half2_rn(c[nt][0], c[nt][1]);
        if (r1 < NN)
            *(__half2*)(g_h1h + (size_t)r1 * 128 + col) =
                __floats2half2_rn(c[nt][2], c[nt][3]);
    }

    // fused att1: per-head dot products. head h = nt>>1; cols j0=nt*8+t4*2, j0+1
    float asr0[8], adr0[8], asr1[8], adr1[8];
    #pragma unroll
    for (int h = 0; h < 8; h++) asr0[h] = adr0[h] = asr1[h] = adr1[h] = 0.f;
    #pragma unroll
    for (int nt = 0; nt < 16; nt++) {
        int h = nt >> 1;
        int j0 = nt * 8 + t4 * 2;
        float s0 = As1[j0], s1 = As1[j0 + 1];
        float d0 = Ad1[j0], d1 = Ad1[j0 + 1];
        asr0[h] += c[nt][0] * s0 + c[nt][1] * s1;
        adr0[h] += c[nt][0] * d0 + c[nt][1] * d1;
        asr1[h] += c[nt][2] * s0 + c[nt][3] * s1;
        adr1[h] += c[nt][2] * d0 + c[nt][3] * d1;
    }
    #pragma unroll
    for (int off = 1; off <= 2; off <<= 1) {
        #pragma unroll
        for (int h = 0; h < 8; h++) {
            asr0[h] += __shfl_xor_sync(0xffffffffu, asr0[h], off);
            adr0[h] += __shfl_xor_sync(0xffffffffu, adr0[h], off);
            asr1[h] += __shfl_xor_sync(0xffffffffu, asr1[h], off);
            adr1[h] += __shfl_xor_sync(0xffffffffu, adr1[h], off);
        }
    }
    // each t4 writes heads {2*t4, 2*t4+1} as float2
    int h0 = t4 * 2;
    if (r0 < NN) {
        *(float2*)(g_as1 + r0 * 8 + h0) = make_float2(asr0[h0], asr0[h0 + 1]);
        *(float2*)(g_ad1 + r0 * 8 + h0) = make_float2(adr0[h0], adr0[h0 + 1]);
    }
    if (r1 < NN) {
        *(float2*)(g_as1 + r1 * 8 + h0) = make_float2(asr1[h0], asr1[h0 + 1]);
        *(float2*)(g_ad1 + r1 * 8 + h0) = make_float2(adr1[h0], adr1[h0 + 1]);
    }
}

// ---------------- CSR build --------------------------------------------------
__global__ void count_k(const int* __restrict__ ei) {
    int e = blockIdx.x * blockDim.x + threadIdx.x;
    if (e >= EE) return;
    int d = ei[EE + e];
    if ((unsigned)d < NN) atomicAdd(&g_cnt[d], 1);
}

__global__ void scan1_k() {
    __shared__ int wsum[32];
    int n = blockIdx.x * 1024 + threadIdx.x;
    int lane = threadIdx.x & 31;
    int wid = threadIdx.x >> 5;
    int v = (n < NN) ? g_cnt[n] : 0;
    int x = v;
    #pragma unroll
    for (int off = 1; off < 32; off <<= 1) {
        int y = __shfl_up_sync(0xffffffffu, x, off);
        if (lane >= off) x += y;
    }
    if (lane == 31) wsum[wid] = x;
    __syncthreads();
    if (wid == 0) {
        int s = wsum[lane];
        #pragma unroll
        for (int off = 1; off < 32; off <<= 1) {
            int y = __shfl_up_sync(0xffffffffu, s, off);
            if (lane >= off) s += y;
        }
        wsum[lane] = s;
    }
    __syncthreads();
    int incl = x + (wid > 0 ? wsum[wid - 1] : 0);
    if (n < NN) g_rowstart[n] = incl - v;
    if (threadIdx.x == 1023) g_bsum[blockIdx.x] = incl;
}

__global__ void scan2_k() {
    __shared__ int wsum[4];
    int t = threadIdx.x;
    int lane = t & 31;
    int wid = t >> 5;
    int v = (t < NB) ? g_bsum[t] : 0;
    int x = v;
    #pragma unroll
    for (int off = 1; off < 32; off <<= 1) {
        int y = __shfl_up_sync(0xffffffffu, x, off);
        if (lane >= off) x += y;
    }
    if (lane == 31) wsum[wid] = x;
    __syncthreads();
    int pre = 0;
    for (int w = 0; w < wid; w++) pre += wsum[w];
    int incl = x + pre;
    if (t < NB) g_boff[t] = incl - v;
    if (t == NB - 1) g_rowstart[NN] = incl;
}

__global__ void scan3_k() {
    int n = blockIdx.x * 1024 + threadIdx.x;
    if (n >= NN) return;
    int r = g_rowstart[n] + g_boff[blockIdx.x];
    g_rowstart[n] = r;
    g_cursor[n] = r;
}

__global__ void fill_k(const int* __restrict__ ei) {
    int e = blockIdx.x * blockDim.x + threadIdx.x;
    if (e >= EE) return;
    int s = ei[e];
    int d = ei[EE + e];
    if ((unsigned)s >= NN || (unsigned)d >= NN) return;
    int pos = atomicAdd(&g_cursor[d], 1);
    g_csrc[pos] = s;
}

// ---------------- layer-1 aggregation: warp per dst node, 4-way MLP ---------
__global__ void agg1_k(const float* __restrict__ B1) {
    int node = (blockIdx.x * blockDim.x + threadIdx.x) >> 5;
    if (node >= NN) return;
    int lane = threadIdx.x & 31;
    int h = lane >> 2;

    const uint2* Hh = (const uint2*)g_h1h;  // 4 halfs per uint2; 32 per row

    float adh = g_ad1[node * 8 + h];
    float w = __expf(lrelu(g_as1[node * 8 + h] + adh));
    uint2 raw = Hh[(size_t)node * 32 + lane];
    float2 f0 = __half22float2(*(const __half2*)&raw.x);
    float2 f1 = __half22float2(*(const __half2*)&raw.y);
    float4 acc = make_float4(w * f0.x, w * f0.y, w * f1.x, w * f1.y);
    float ssum = w;

    int e = g_rowstart[node];
    int end = g_rowstart[node + 1];
    for (; e + 3 < end; e += 4) {
        int s0 = g_csrc[e], s1 = g_csrc[e + 1], s2 = g_csrc[e + 2], s3 = g_csrc[e + 3];
        float a0 = g_as1[s0 * 8 + h], a1 = g_as1[s1 * 8 + h];
        float a2 = g_as1[s2 * 8 + h], a3 = g_as1[s3 * 8 + h];
        uint2 r0 = Hh[(size_t)s0 * 32 + lane];
        uint2 r1 = Hh[(size_t)s1 * 32 + lane];
        uint2 r2 = Hh[(size_t)s2 * 32 + lane];
        uint2 r3 = Hh[(size_t)s3 * 32 + lane];
        float w0 = __expf(lrelu(a0 + adh));
        float w1 = __expf(lrelu(a1 + adh));
        float w2 = __expf(lrelu(a2 + adh));
        float w3 = __expf(lrelu(a3 + adh));
        float2 x0 = __half22float2(*(const __half2*)&r0.x), y0 = __half22float2(*(const __half2*)&r0.y);
        float2 x1 = __half22float2(*(const __half2*)&r1.x), y1 = __half22float2(*(const __half2*)&r1.y);
        float2 x2 = __half22float2(*(const __half2*)&r2.x), y2 = __half22float2(*(const __half2*)&r2.y);
        float2 x3 = __half22float2(*(const __half2*)&r3.x), y3 = __half22float2(*(const __half2*)&r3.y);
        acc.x += w0 * x0.x + w1 * x1.x + w2 * x2.x + w3 * x3.x;
        acc.y += w0 * x0.y + w1 * x1.y + w2 * x2.y + w3 * x3.y;
        acc.z += w0 * y0.x + w1 * y1.x + w2 * y2.x + w3 * y3.x;
        acc.w += w0 * y0.y + w1 * y1.y + w2 * y2.y + w3 * y3.y;
        ssum += w0 + w1 + w2 + w3;
    }
    for (; e < end; e++) {
        int s = g_csrc[e];
        float a = g_as1[s * 8 + h] + adh;
        float we = __expf(lrelu(a));
        uint2 rv = Hh[(size_t)s * 32 + lane];
        float2 v0 = __half22float2(*(const __half2*)&rv.x);
        float2 v1 = __half22float2(*(const __half2*)&rv.y);
        acc.x += we * v0.x;
        acc.y += we * v0.y;
        acc.z += we * v1.x;
        acc.w += we * v1.y;
        ssum += we;
    }
    float inv = 1.f / ssum;
    float4 b = ((const float4*)B1)[lane];
    float ox = eluf(acc.x * inv + b.x);
    float oy = eluf(acc.y * inv + b.y);
    float oz = eluf(acc.z * inv + b.z);
    float ow = eluf(acc.w * inv + b.w);
    uint2 st;
    *(__half2*)&st.x = __floats2half2_rn(ox, oy);
    *(__half2*)&st.y = __floats2half2_rn(oz, ow);
    ((uint2*)g_out1h)[(size_t)node * 32 + lane] = st;
}

// ---------------- GEMM2 + fused att2 logits ---------------------------------
__global__ void gemm2_k(const float* __restrict__ W,
                        const float* __restrict__ As2, const float* __restrict__ Ad2) {
    __shared__ __align__(16) float Xs[32 * 128];
    int row0 = blockIdx.x * 32;
    int tid = threadIdx.x;

    const uint4* Xg = (const uint4*)(g_out1h + (size_t)row0 * 128);
    for (int i = tid; i < 512; i += 64) {
        uint4 rv = Xg[i];
        float* dst = Xs + i * 8;
        const unsigned int* rr = (const unsigned int*)&rv;
        #pragma unroll
        for (int q = 0; q < 4; q++) {
            float2 t = __half22float2(*(const __half2*)&rr[q]);
            dst[q * 2] = t.x;
            dst[q * 2 + 1] = t.y;
        }
    }
    __syncthreads();

    int j = tid;
    bool valid = j < 40;
    unsigned long long acc[32];
    #pragma unroll
    for (int r = 0; r < 32; r++) acc[r] = 0ULL;

    const ulonglong2* Xp = (const ulonglong2*)Xs;
    for (int k4 = 0; k4 < 32; k4++) {
        int kb = k4 * 4;
        float w0 = valid ? W[(kb + 0) * 40 + j] : 0.f;
        float w1 = valid ? W[(kb + 1) * 40 + j] : 0.f;
        float w2 = valid ? W[(kb + 2) * 40 + j] : 0.f;
        float w3 = valid ? W[(kb + 3) * 40 + j] : 0.f;
        unsigned long long w01 = pk2(w0, w1), w23 = pk2(w2, w3);
        #pragma unroll
        for (int r = 0; r < 32; r++) {
            ulonglong2 xv = Xp[r * 32 + k4];
            fma2(acc[r], xv.x, w01);
            fma2(acc[r], xv.y, w23);
        }
    }

    float v[32];
    #pragma unroll
    for (int r = 0; r < 32; r++) {
        float lo, hi;
        upk2(acc[r], lo, hi);
        v[r] = lo + hi;
    }
    if (valid) {
        #pragma unroll
        for (int r = 0; r < 32; r++)
            g_h2h[(size_t)(row0 + r) * 40 + j] = __float2half(v[r]);
    }

    // fused att2: stage v*as2[j] / v*ad2[j] into smem (reuse Xs), reduce over j
    __syncthreads();   // everyone done reading Xs
    float sj = valid ? As2[j] : 0.f;
    float dj = valid ? Ad2[j] : 0.f;
    #pragma unroll
    for (int r = 0; r < 32; r++) {
        Xs[j * 32 + r] = v[r] * sj;
        Xs[2048 + j * 32 + r] = v[r] * dj;
    }
    __syncthreads();
    if (tid < 32) {
        int r = tid;
        float aS = 0.f, aD = 0.f;
        #pragma unroll
        for (int q = 0; q < 40; q++) {
            aS += Xs[q * 32 + r];
            aD += Xs[2048 + q * 32 + r];
        }
        g_a2s[row0 + r] = aS;
        g_a2d[row0 + r] = aD;
    }
}

// ---------------- layer-2 aggregation + ELU + log_softmax: warp per node ----
__global__ void agg2_k(float* __restrict__ out, const float* __restrict__ B2) {
    int node = (blockIdx.x * blockDim.x + threadIdx.x) >> 5;
    if (node >= NN) return;
    int lane = threadIdx.x & 31;
    int half = lane >> 4;
    int l = lane & 15;
    bool act = l < 10;

    const uint2* Hh = (const uint2*)g_h2h;  // 10 uint2 per row (40 halfs)

    float a2d = g_a2d[node];
    float4 acc = make_float4(0.f, 0.f, 0.f, 0.f);
    float ssum = 0.f;

    if (half == 0) {
        float w = __expf(lrelu(g_a2s[node] + a2d));
        if (act) {
            uint2 raw = Hh[(size_t)node * 10 + l];
            float2 f0 = __half22float2(*(const __half2*)&raw.x);
            float2 f1 = __half22float2(*(const __half2*)&raw.y);
            acc = make_float4(w * f0.x, w * f0.y, w * f1.x, w * f1.y);
        }
        ssum = w;
    }

    int beg = g_rowstart[node] + half;
    int end = g_rowstart[node + 1];
    int e = beg;
    for (; e + 2 < end; e += 4) {
        int s0 = g_csrc[e], s1 = g_csrc[e + 2];
        float a0 = g_a2s[s0], a1 = g_a2s[s1];
        uint2 r0, r1;
        if (act) {
            r0 = Hh[(size_t)s0 * 10 + l];
            r1 = Hh[(size_t)s1 * 10 + l];
        }
        float w0 = __expf(lrelu(a0 + a2d));
        float w1 = __expf(lrelu(a1 + a2d));
        if (act) {
            float2 x0 = __half22float2(*(const __half2*)&r0.x), y0 = __half22float2(*(const __half2*)&r0.y);
            float2 x1 = __half22float2(*(const __half2*)&r1.x), y1 = __half22float2(*(const __half2*)&r1.y);
            acc.x += w0 * x0.x + w1 * x1.x;
            acc.y += w0 * x0.y + w1 * x1.y;
            acc.z += w0 * y0.x + w1 * y1.x;
            acc.w += w0 * y0.y + w1 * y1.y;
        }
        ssum += w0 + w1;
    }
    for (; e < end; e += 2) {
        int s = g_csrc[e];
        float w = __expf(lrelu(g_a2s[s] + a2d));
        if (act) {
            uint2 raw = Hh[(size_t)s * 10 + l];
            float2 f0 = __half22float2(*(const __half2*)&raw.x);
            float2 f1 = __half22float2(*(const __half2*)&raw.y);
            acc.x += w * f0.x;
            acc.y += w * f0.y;
            acc.z += w * f1.x;
            acc.w += w * f1.y;
        }
        ssum += w;
    }
    acc.x += __shfl_xor_sync(0xffffffffu, acc.x, 16);
    acc.y += __shfl_xor_sync(0xffffffffu, acc.y, 16);
    acc.z += __shfl_xor_sync(0xffffffffu, acc.z, 16);
    acc.w += __shfl_xor_sync(0xffffffffu, acc.w, 16);
    ssum  += __shfl_xor_sync(0xffffffffu, ssum, 16);

    float inv = 1.f / ssum;
    float4 t = make_float4(0.f, 0.f, 0.f, 0.f);
    if (act) {
        float4 b = ((const float4*)B2)[l];
        t.x = eluf(acc.x * inv + b.x);
        t.y = eluf(acc.y * inv + b.y);
        t.z = eluf(acc.z * inv + b.z);
        t.w = eluf(acc.w * inv + b.w);
    }
    float mx = act ? fmaxf(fmaxf(t.x, t.y), fmaxf(t.z, t.w)) : -3.0e38f;
    #pragma unroll
    for (int off = 16; off; off >>= 1) mx = fmaxf(mx, __shfl_xor_sync(0xffffffffu, mx, off));
    float se = (act && half == 0)
                   ? (__expf(t.x - mx) + __expf(t.y - mx) + __expf(t.z - mx) + __expf(t.w - mx))
                   : 0.f;
    #pragma unroll
    for (int off = 16; off; off >>= 1) se += __shfl_xor_sync(0xffffffffu, se, off);
    float lse = mx + logf(se);
    if (act && half == 0) {
        float4 o = make_float4(t.x - lse, t.y - lse, t.z - lse, t.w - lse);
        ((float4*)out)[(size_t)node * 10 + l] = o;
    }
}

// ---------------- launch ----------------------------------------------------
extern "C" void kernel_launch(void* const* d_in, const int* in_sizes, int n_in,
                              void* d_out, int out_size) {
    const float* x = (const float*)d_in[0];
    const int* ei = (const int*)d_in[2];
    const float* W1 = (const float*)d_in[3];
    const float* as1 = (const float*)d_in[4];
    const float* ad1 = (const float*)d_in[5];
    const float* b1 = (const float*)d_in[6];
    const float* W2 = (const float*)d_in[7];
    const float* as2 = (const float*)d_in[8];
    const float* ad2 = (const float*)d_in[9];
    const float* b2 = (const float*)d_in[10];
    float* out = (float*)d_out;

    void* p_cnt;
    cudaGetSymbolAddress(&p_cnt, g_cnt);

    cudaFuncSetAttribute(gemm1_k, cudaFuncAttributeMaxDynamicSharedMemorySize, G1_SMEM);

    // fork: CSR build chain on side stream, independent of gemm1
    cudaEventRecord(g_ss.ea, 0);
    cudaStreamWaitEvent(g_ss.s, g_ss.ea, 0);
    cudaMemsetAsync(p_cnt, 0, NN * sizeof(int), g_ss.s);
    count_k<<<(EE + 255) / 256, 256, 0, g_ss.s>>>(ei);
    scan1_k<<<NB, 1024, 0, g_ss.s>>>();
    scan2_k<<<1, 128, 0, g_ss.s>>>();
    scan3_k<<<NB, 1024, 0, g_ss.s>>>();
    fill_k<<<(EE + 255) / 256, 256, 0, g_ss.s>>>(ei);
    cudaEventRecord(g_ss.eb, g_ss.s);

    // main stream: feature chain (att1 fused into gemm1)
    gemm1_k<<<G1_GRID, 128, G1_SMEM>>>(x, W1, as1, ad1);

    // join, then aggregation onward
    cudaStreamWaitEvent(0, g_ss.eb, 0);
    agg1_k<<<(NN * 32 + 255) / 256, 256>>>(b1);
    gemm2_k<<<NN / 32, 64>>>(W2, as2, ad2);
    agg2_k<<<(NN * 32 + 255) / 256, 256>>>(out, b2);
}